// round 8
// baseline (speedup 1.0000x reference)
#include <cuda_runtime.h>
#include <cuda_fp16.h>

#define NN 50000
#define EE 800000
#define FD 128      // H*HID
#define EDD 16
#define HIDD 32
#define HH 4
#define OUTD 64
#define NEGS 0.1f

// ---------------- scratch (device globals) -----------------------------------
__device__ float  g_f0[NN * HIDD];
__device__ float  g_f1[NN * HIDD];
__device__ float  g_f2[NN * HIDD];
__device__ float  g_xl[(size_t)NN * FD];
__device__ float  g_xr[(size_t)NN * FD];
__device__ int    g_deg[NN];
__device__ int    g_cursor[NN];
__device__ int    g_row[NN + 1];
__device__ int    g_srcs[EE];
__device__ int    g_perm[EE];
__device__ __half g_eap[(size_t)EE * FD];   // per-layer edge projection (fp16)

__device__ __forceinline__ float lrelu(float v) { return fmaxf(v, NEGS * v); }

// ------ launch 0: embed (Linear+BN+LeakyReLU) + dst histogram -----------------
__global__ void k_embed_hist(const float* __restrict__ x, const float* __restrict__ W0,
                             const float* __restrict__ b0, const float* __restrict__ bng,
                             const float* __restrict__ bnb, const float* __restrict__ bnm,
                             const float* __restrict__ bnv, const int* __restrict__ ei) {
    __shared__ float W0t[128 * 32];   // [k][j]
    int tid = threadIdx.x;
    for (int i = tid; i < 128 * 32; i += blockDim.x) {
        int k = i >> 5, j = i & 31;
        W0t[i] = W0[j * 128 + k];
    }
    __syncthreads();
    int warp = tid >> 5, lane = tid & 31;
    float sc = bng[lane] * rsqrtf(bnv[lane] + 1e-5f);
    float bb = bnb[lane], bm = bnm[lane], b00 = b0[lane];
#pragma unroll
    for (int it = 0; it < 8; it++) {
        int n = blockIdx.x * 64 + it * 8 + warp;
        if (n < NN) {
            const float* xr_ = x + (size_t)n * 128;
            float acc = 0.f;
#pragma unroll 8
            for (int k = 0; k < 128; k++) acc += xr_[k] * W0t[k * 32 + lane];
            acc += b00;
            acc = (acc - bm) * sc + bb;
            g_f0[n * 32 + lane] = lrelu(acc);
        }
    }
    // histogram of dst degrees (g_deg zeroed by previous call's k_scan; zero-init on first)
    int gs = blockIdx.x * blockDim.x + tid;
    int stride = gridDim.x * blockDim.x;
    for (int e = gs; e < EE; e += stride) atomicAdd(&g_deg[ei[EE + e]], 1);
}

// ------ launch 1: exclusive scan -> g_row; resets deg/cursor for next call ----
__global__ void k_scan() {
    __shared__ int wsum[32];
    __shared__ int carry;
    int tid = threadIdx.x, lane = tid & 31, w = tid >> 5;
    if (tid == 0) { carry = 0; g_row[0] = 0; }
    __syncthreads();
    for (int t0 = 0; t0 < NN; t0 += 1024) {
        int i = t0 + tid;
        int v = (i < NN) ? g_deg[i] : 0;
        int s = v;
#pragma unroll
        for (int o = 1; o < 32; o <<= 1) {
            int u = __shfl_up_sync(0xffffffffu, s, o);
            if (lane >= o) s += u;
        }
        if (lane == 31) wsum[w] = s;
        __syncthreads();
        if (w == 0) {
            int ws = wsum[lane];
#pragma unroll
            for (int o = 1; o < 32; o <<= 1) {
                int u = __shfl_up_sync(0xffffffffu, ws, o);
                if (lane >= o) ws += u;
            }
            wsum[lane] = ws;
        }
        __syncthreads();
        int inc = s + (w > 0 ? wsum[w - 1] : 0) + carry;
        if (i < NN) {
            g_row[i + 1] = inc;
            g_deg[i] = 0;       // reset for next call's histogram
            g_cursor[i] = 0;    // reset for this call's scatter
        }
        __syncthreads();
        if (tid == 1023) carry = inc;
        __syncthreads();
    }
}

// ------ launch 2: scatter edges into CSR order --------------------------------
__global__ void k_scatter(const int* __restrict__ ei) {
    int e = blockIdx.x * blockDim.x + threadIdx.x;
    if (e >= EE) return;
    int dst = ei[EE + e];
    int pos = g_row[dst] + atomicAdd(&g_cursor[dst], 1);
    g_srcs[pos] = ei[e];
    g_perm[pos] = e;
}

// ------ edge projection GEMM: g_eap = eattr @ We^T (fp16 out) ------------------
__global__ __launch_bounds__(256)
void k_eaproj(const float* __restrict__ eattr, const float* __restrict__ We) {
    __shared__ float WeT[16 * 128];   // [d][j]
    __shared__ float4 eat[32 * 4];    // [edge][dp], dp covers dims 4dp..4dp+3
    int tid = threadIdx.x;
    for (int i = tid; i < 16 * 128; i += 256) WeT[i] = We[(i & 127) * 16 + (i >> 7)];
    int e0 = blockIdx.x * 32;
    for (int i = tid; i < 512; i += 256)
        ((float*)eat)[i] = eattr[(size_t)e0 * 16 + i];
    __syncthreads();
    int j = tid & 127, hf = tid >> 7;
    float acc[16];
#pragma unroll
    for (int e = 0; e < 16; e++) acc[e] = 0.f;
#pragma unroll
    for (int dp = 0; dp < 4; dp++) {
        float w0 = WeT[(4 * dp + 0) * 128 + j];
        float w1 = WeT[(4 * dp + 1) * 128 + j];
        float w2 = WeT[(4 * dp + 2) * 128 + j];
        float w3 = WeT[(4 * dp + 3) * 128 + j];
#pragma unroll
        for (int e = 0; e < 16; e++) {
            float4 ev = eat[(hf * 16 + e) * 4 + dp];   // broadcast
            acc[e] += ev.x * w0 + ev.y * w1 + ev.z * w2 + ev.w * w3;
        }
    }
#pragma unroll
    for (int e = 0; e < 16; e++)
        g_eap[(size_t)(e0 + hf * 16 + e) * 128 + j] = __float2half(acc[e]);
}

// ------ node transforms (unchanged) -------------------------------------------
__global__ void k_xlxr(const float* __restrict__ feat,
                       const float* __restrict__ Wl, const float* __restrict__ bl,
                       const float* __restrict__ Wr, const float* __restrict__ br) {
    __shared__ float WlT[32 * 128];
    __shared__ float WrT[32 * 128];
    __shared__ float tile[32 * 32];
    int tid = threadIdx.x;
    for (int i = tid; i < 32 * 128; i += blockDim.x) {
        int k = i >> 7, j = i & 127;
        WlT[i] = Wl[j * 32 + k];
        WrT[i] = Wr[j * 32 + k];
    }
    int nbase = blockIdx.x * 32;
    for (int i = tid; i < 32 * 32; i += blockDim.x) {
        int n = nbase + (i >> 5);
        tile[i] = (n < NN) ? feat[n * 32 + (i & 31)] : 0.f;
    }
    __syncthreads();
    int j = tid & 127;
    int half = tid >> 7;
    float accl[16], accr[16];
#pragma unroll
    for (int n = 0; n < 16; n++) { accl[n] = 0.f; accr[n] = 0.f; }
#pragma unroll
    for (int k = 0; k < 32; k++) {
        float wl = WlT[k * 128 + j];
        float wr = WrT[k * 128 + j];
        const float* tr = &tile[(half * 16) * 32 + k];
#pragma unroll
        for (int n = 0; n < 16; n++) {
            float fv = tr[n * 32];
            accl[n] += fv * wl;
            accr[n] += fv * wr;
        }
    }
    float blj = bl[j], brj = br[j];
#pragma unroll
    for (int n = 0; n < 16; n++) {
        int node = nbase + half * 16 + n;
        if (node < NN) {
            g_xl[(size_t)node * 128 + j] = accl[n] + blj;
            g_xr[(size_t)node * 128 + j] = accr[n] + brj;
        }
    }
}

// ------ fused GAT layer: warp per node, precomputed EA projection --------------
// lane owns channels 4*lane..4*lane+3 (head = lane>>3).
#define GAT_NPW 4
__global__ __launch_bounds__(256, 2)
void k_gat(const float* __restrict__ att, const float* __restrict__ bias,
           float* __restrict__ out) {
    int tid = threadIdx.x, warp = tid >> 5, lane = tid & 31;
    float4 att4 = ((const float4*)att)[lane];
    float4 bias4 = make_float4(0.f, 0.f, 0.f, 0.f);
    if (lane < 8) bias4 = ((const float4*)bias)[lane];

    for (int t = 0; t < GAT_NPW; t++) {
        int n = (blockIdx.x * 8 + warp) * GAT_NPW + t;
        if (n >= NN) return;
        int rs = g_row[n], deg = g_row[n + 1] - rs;
        float4 xr4  = ((const float4*)(g_xr + (size_t)n * 128))[lane];
        float4 xls4 = ((const float4*)(g_xl + (size_t)n * 128))[lane];
        float4 num   = make_float4(0.f, 0.f, 0.f, 0.f);
        float4 easum = make_float4(0.f, 0.f, 0.f, 0.f);
        float den = 0.f;

        for (int c0 = 0; c0 < deg; c0 += 8) {
            int cnt = deg - c0; if (cnt > 8) cnt = 8;
            // lanes 0-7: src idx, lanes 8-15: CSR->orig perm
            int idx = 0;
            if (lane < 8) { if (c0 + lane < deg) idx = g_srcs[rs + c0 + lane]; }
            else if (lane < 16) { if (c0 + lane - 8 < deg) idx = g_perm[rs + c0 + lane - 8]; }

            float4 xl[8];
            uint2  eah[8];
#pragma unroll
            for (int e = 0; e < 8; e++) {
                if (e < cnt) {
                    int se = __shfl_sync(0xffffffffu, idx, e);
                    int pe = __shfl_sync(0xffffffffu, idx, 8 + e);
                    xl[e]  = __ldg((const float4*)(g_xl + (size_t)se * 128) + lane);
                    eah[e] = __ldg((const uint2*)(g_eap + (size_t)pe * 128) + lane);
                }
            }
#pragma unroll
            for (int e = 0; e < 8; e++) {
                if (e >= cnt) break;
                float2 lo = __half22float2(*(const __half2*)&eah[e].x);
                float2 hi = __half22float2(*(const __half2*)&eah[e].y);
                easum.x += lo.x; easum.y += lo.y; easum.z += hi.x; easum.w += hi.y;
                float t0 = lrelu(xl[e].x + xr4.x + lo.x) * att4.x;
                float t1 = lrelu(xl[e].y + xr4.y + lo.y) * att4.y;
                float t2 = lrelu(xl[e].z + xr4.z + hi.x) * att4.z;
                float t3 = lrelu(xl[e].w + xr4.w + hi.y) * att4.w;
                float s = (t0 + t1) + (t2 + t3);
                s += __shfl_xor_sync(0xffffffffu, s, 1);
                s += __shfl_xor_sync(0xffffffffu, s, 2);
                s += __shfl_xor_sync(0xffffffffu, s, 4);
                float ex = __expf(s);
                num.x += ex * xl[e].x; num.y += ex * xl[e].y;
                num.z += ex * xl[e].z; num.w += ex * xl[e].w;
                den += ex;
            }
        }

        // self-loop: projected attr = mean of incoming projections (linearity)
        float invd = 1.f / fmaxf((float)deg, 1.f);
        {
            float t0 = lrelu(xls4.x + xr4.x + easum.x * invd) * att4.x;
            float t1 = lrelu(xls4.y + xr4.y + easum.y * invd) * att4.y;
            float t2 = lrelu(xls4.z + xr4.z + easum.z * invd) * att4.z;
            float t3 = lrelu(xls4.w + xr4.w + easum.w * invd) * att4.w;
            float s = (t0 + t1) + (t2 + t3);
            s += __shfl_xor_sync(0xffffffffu, s, 1);
            s += __shfl_xor_sync(0xffffffffu, s, 2);
            s += __shfl_xor_sync(0xffffffffu, s, 4);
            float ex = __expf(s);
            num.x += ex * xls4.x; num.y += ex * xls4.y;
            num.z += ex * xls4.z; num.w += ex * xls4.w;
            den += ex;
        }

        // normalize per head, mean heads, bias, store
        float r = 1.f / den;
        float4 p;
        p.x = num.x * r; p.y = num.y * r; p.z = num.z * r; p.w = num.w * r;
        p.x += __shfl_xor_sync(0xffffffffu, p.x, 8);
        p.y += __shfl_xor_sync(0xffffffffu, p.y, 8);
        p.z += __shfl_xor_sync(0xffffffffu, p.z, 8);
        p.w += __shfl_xor_sync(0xffffffffu, p.w, 8);
        p.x += __shfl_xor_sync(0xffffffffu, p.x, 16);
        p.y += __shfl_xor_sync(0xffffffffu, p.y, 16);
        p.z += __shfl_xor_sync(0xffffffffu, p.z, 16);
        p.w += __shfl_xor_sync(0xffffffffu, p.w, 16);
        if (lane < 8) {
            float4 o;
            o.x = 0.25f * p.x + bias4.x;
            o.y = 0.25f * p.y + bias4.y;
            o.z = 0.25f * p.z + bias4.z;
            o.w = 0.25f * p.w + bias4.w;
            ((float4*)(out + (size_t)n * 32))[lane] = o;
        }
    }
}

// ------ output head -------------------------------------------------------------
__global__ void k_final(const float* __restrict__ feat, const float* __restrict__ Wout,
                        const float* __restrict__ bout, float* __restrict__ y) {
    __shared__ float WT[32 * 64];   // [c][o]
    int tid = threadIdx.x;
    for (int i = tid; i < 32 * 64; i += blockDim.x) {
        int c = i >> 6, o = i & 63;
        WT[i] = Wout[o * 32 + c];
    }
    __syncthreads();
    int o = tid & 63;
    float bo = bout[o];
#pragma unroll
    for (int it = 0; it < 16; it++) {
        int n = blockIdx.x * 64 + it * 4 + (tid >> 6);
        if (n >= NN) return;
        const float* fr = feat + n * 32;
        float acc = 0.f;
#pragma unroll
        for (int c = 0; c < 32; c++) acc += fr[c] * WT[c * 64 + o];
        acc += bo;
        y[(size_t)n * 64 + o] = lrelu(acc);
    }
}

// =============================================================================
extern "C" void kernel_launch(void* const* d_in, const int* in_sizes, int n_in,
                              void* d_out, int out_size) {
    const float* x     = (const float*)d_in[0];
    const int*   ei    = (const int*)d_in[1];
    const float* eattr = (const float*)d_in[2];
    const float* W0    = (const float*)d_in[3];
    const float* b0    = (const float*)d_in[4];
    const float* bng   = (const float*)d_in[5];
    const float* bnb   = (const float*)d_in[6];
    const float* bnm   = (const float*)d_in[7];
    const float* bnv   = (const float*)d_in[8];
    const float* Wl[2]   = {(const float*)d_in[9],  (const float*)d_in[16]};
    const float* bl[2]   = {(const float*)d_in[10], (const float*)d_in[17]};
    const float* Wr[2]   = {(const float*)d_in[11], (const float*)d_in[18]};
    const float* br[2]   = {(const float*)d_in[12], (const float*)d_in[19]};
    const float* We[2]   = {(const float*)d_in[13], (const float*)d_in[20]};
    const float* att[2]  = {(const float*)d_in[14], (const float*)d_in[21]};
    const float* bias[2] = {(const float*)d_in[15], (const float*)d_in[22]};
    const float* Wout  = (const float*)d_in[23];
    const float* bout  = (const float*)d_in[24];
    float* y = (float*)d_out;

    float *f0, *f1, *f2;
    cudaGetSymbolAddress((void**)&f0, g_f0);
    cudaGetSymbolAddress((void**)&f1, g_f1);
    cudaGetSymbolAddress((void**)&f2, g_f2);

    k_embed_hist<<<(NN + 63) / 64, 256>>>(x, W0, b0, bng, bnb, bnm, bnv, ei);        // 0
    k_scan<<<1, 1024>>>();                                                           // 1
    k_scatter<<<(EE + 255) / 256, 256>>>(ei);                                        // 2

    const float* fin[2]  = {f0, f1};
    float*       fout[2] = {f1, f2};
    for (int l = 0; l < 2; l++) {
        k_eaproj<<<EE / 32, 256>>>(eattr, We[l]);                                    // 3 <- profiled, 6
        k_xlxr<<<(NN + 31) / 32, 256>>>(fin[l], Wl[l], bl[l], Wr[l], br[l]);         // 4, 7
        k_gat<<<(NN + 8 * GAT_NPW - 1) / (8 * GAT_NPW), 256>>>(
            att[l], bias[l], fout[l]);                                               // 5, 8
    }
    k_final<<<(NN + 63) / 64, 256>>>(f2, Wout, bout, y);                             // 9
}

// round 9
// speedup vs baseline: 1.5269x; 1.5269x over previous
#include <cuda_runtime.h>
#include <cuda_fp16.h>

#define NN 50000
#define EE 800000
#define ET (EE + NN)
#define FD 128      // H*HID
#define EDD 16      // edge_dim
#define HIDD 32
#define HH 4
#define OUTD 64
#define NEGS 0.1f

typedef unsigned long long ull;

// ---------------- scratch (device globals) -----------------------------------
__device__ float  g_f0[NN * HIDD];
__device__ float  g_f1[NN * HIDD];
__device__ float  g_f2[NN * HIDD];
__device__ float  g_xl[(size_t)NN * FD];
__device__ float  g_xr[(size_t)NN * FD];
__device__ __half g_xrh[(size_t)NN * FD];   // fp16 copy of xr for alpha gathers
__device__ float  g_loop[NN * EDD];
__device__ float  g_cnt[NN];
__device__ float  g_ex[(size_t)ET * HH];
__device__ float  g_den[2][NN * HH];

__device__ __forceinline__ float lrelu(float v) { return fmaxf(v, NEGS * v); }

__device__ __forceinline__ void fma2(ull& acc, ull a, ull b) {
    asm("fma.rn.f32x2 %0, %1, %2, %0;" : "+l"(acc) : "l"(a), "l"(b));
}
__device__ __forceinline__ float2 upk(ull v) {
    float2 r; asm("mov.b64 {%0,%1}, %2;" : "=f"(r.x), "=f"(r.y) : "l"(v)); return r;
}
__device__ __forceinline__ void red4(float* addr, float4 v) {
    asm volatile("red.global.add.v4.f32 [%0], {%1,%2,%3,%4};"
                 :: "l"(addr), "f"(v.x), "f"(v.y), "f"(v.z), "f"(v.w) : "memory");
}

// ------ launch 0: embed + zero loop/cnt/den + seed outputs with bias ---------
__global__ void k_embed_plus(const float* __restrict__ x, const float* __restrict__ W0,
                             const float* __restrict__ b0, const float* __restrict__ bng,
                             const float* __restrict__ bnb, const float* __restrict__ bnm,
                             const float* __restrict__ bnv,
                             const float* __restrict__ bias0, const float* __restrict__ bias1) {
    __shared__ float W0t[128 * 32];   // [k][j]
    int tid = threadIdx.x;
    for (int i = tid; i < 128 * 32; i += blockDim.x) {
        int k = i >> 5, j = i & 31;
        W0t[i] = W0[j * 128 + k];
    }
    __syncthreads();
    int warp = tid >> 5, lane = tid & 31;
    float sc = bng[lane] * rsqrtf(bnv[lane] + 1e-5f);
    float bb = bnb[lane], bm = bnm[lane], b00 = b0[lane];
#pragma unroll
    for (int it = 0; it < 8; it++) {
        int n = blockIdx.x * 64 + it * 8 + warp;
        if (n < NN) {
            const float* xr_ = x + (size_t)n * 128;
            float acc = 0.f;
#pragma unroll 8
            for (int k = 0; k < 128; k++) acc += xr_[k] * W0t[k * 32 + lane];
            acc += b00;
            acc = (acc - bm) * sc + bb;
            g_f0[n * 32 + lane] = lrelu(acc);
        }
    }
    // side work: zero accumulators (required for per-call idempotency)
    int gs = blockIdx.x * blockDim.x + tid;
    int stride = gridDim.x * blockDim.x;
    float4 z4 = make_float4(0.f, 0.f, 0.f, 0.f);
    for (int i = gs; i < NN * 4; i += stride) ((float4*)g_loop)[i] = z4;
    for (int i = gs; i < NN; i += stride) g_cnt[i] = 0.f;
    for (int i = gs; i < NN * HH; i += stride) { g_den[0][i] = 0.f; g_den[1][i] = 0.f; }
    for (int i = gs; i < NN * HIDD; i += stride) {
        g_f1[i] = bias0[i & 31];
        g_f2[i] = bias1[i & 31];
    }
}

// ------ launch 1: self-loop attr accumulation (vectorized reds) ---------------
__global__ void k_loop_accum(const int* __restrict__ ei, const float* __restrict__ ea) {
    int i = blockIdx.x * blockDim.x + threadIdx.x;
    if (i >= EE * 4) return;
    int e = i >> 2, q = i & 3;
    int dst = ei[EE + e];
    float4 v = ((const float4*)ea)[i];
    red4(&g_loop[dst * EDD + q * 4], v);
    if (q == 0) atomicAdd(&g_cnt[dst], 1.f);
}

// ------ node transforms (also emits fp16 xr copy) ------------------------------
__global__ void k_xlxr(const float* __restrict__ feat,
                       const float* __restrict__ Wl, const float* __restrict__ bl,
                       const float* __restrict__ Wr, const float* __restrict__ br) {
    __shared__ float WlT[32 * 128];
    __shared__ float WrT[32 * 128];
    __shared__ float tile[32 * 32];
    int tid = threadIdx.x;
    for (int i = tid; i < 32 * 128; i += blockDim.x) {
        int k = i >> 7, j = i & 127;
        WlT[i] = Wl[j * 32 + k];
        WrT[i] = Wr[j * 32 + k];
    }
    int nbase = blockIdx.x * 32;
    for (int i = tid; i < 32 * 32; i += blockDim.x) {
        int n = nbase + (i >> 5);
        tile[i] = (n < NN) ? feat[n * 32 + (i & 31)] : 0.f;
    }
    __syncthreads();
    int j = tid & 127;
    int half = tid >> 7;
    float accl[16], accr[16];
#pragma unroll
    for (int n = 0; n < 16; n++) { accl[n] = 0.f; accr[n] = 0.f; }
#pragma unroll
    for (int k = 0; k < 32; k++) {
        float wl = WlT[k * 128 + j];
        float wr = WrT[k * 128 + j];
        const float* tr = &tile[(half * 16) * 32 + k];
#pragma unroll
        for (int n = 0; n < 16; n++) {
            float fv = tr[n * 32];
            accl[n] += fv * wl;
            accr[n] += fv * wr;
        }
    }
    float blj = bl[j], brj = br[j];
#pragma unroll
    for (int n = 0; n < 16; n++) {
        int node = nbase + half * 16 + n;
        if (node < NN) {
            float xr = accr[n] + brj;
            g_xl[(size_t)node * 128 + j] = accl[n] + blj;
            g_xr[(size_t)node * 128 + j] = xr;
            g_xrh[(size_t)node * 128 + j] = __float2half(xr);
        }
    }
}

// ------ pass A: reg-hoisted We (fma2), padded staging, fp16 xr gathers ---------
// lane owns channels 4*lane..4*lane+3 (head = lane>>3); warp does 8 edges; 4 tiles.
#define ALPHA_TILES 4
__global__ __launch_bounds__(256, 2)
void k_alpha(const int* __restrict__ ei, const float* __restrict__ eattr,
             const float* __restrict__ We, const float* __restrict__ att,
             float* __restrict__ den) {
    __shared__ float WeS[16 * 128];                       // [d][channel]
    __shared__ __align__(16) float2 evsp[8][8][22];       // [warp][edge][d] splat, pad 22
    int tid = threadIdx.x;
    for (int i = tid; i < 16 * 128; i += blockDim.x) {
        int d = i >> 7, j = i & 127;
        WeS[i] = We[j * 16 + d];
    }
    __syncthreads();
    int warp = tid >> 5, lane = tid & 31;

    // hoist weights to registers: w01[d] = We[d][4l..4l+1], w23[d] = We[d][4l+2..4l+3]
    ull w01[16], w23[16];
#pragma unroll
    for (int d = 0; d < 16; d++) {
        ulonglong2 w = *(const ulonglong2*)&WeS[d * 128 + 4 * lane];
        w01[d] = w.x; w23[d] = w.y;
    }
    float4 att4 = ((const float4*)att)[lane];

    for (int t = 0; t < ALPHA_TILES; t++) {
        int e0 = (blockIdx.x * (8 * ALPHA_TILES) + t * 8 + warp) * 8;
        if (e0 >= ET) break;

        // edge indices: lanes 0-7 src, lanes 8-15 dst
        int sreg = 0, dreg = 0;
        {
            int le = e0 + (lane & 7);
            if (le < ET) {
                if (lane < 8)       sreg = (le < EE) ? ei[le]      : le - EE;
                else if (lane < 16) dreg = (le < EE) ? ei[EE + le] : le - EE;
            }
        }
        // stage eattr splats: lane -> edge = lane>>2, dims 4q..4q+3 (q = lane&3)
        {
            float4 ea4 = make_float4(0.f, 0.f, 0.f, 0.f);
            int ee = e0 + (lane >> 2);
            if (ee < EE) {
                ea4 = ((const float4*)eattr)[(size_t)ee * 4 + (lane & 3)];
            } else if (ee < ET) {
                int n = ee - EE;
                ea4 = ((const float4*)g_loop)[(size_t)n * 4 + (lane & 3)];
                float inv = 1.f / fmaxf(g_cnt[n], 1.f);
                ea4.x *= inv; ea4.y *= inv; ea4.z *= inv; ea4.w *= inv;
            }
            float2* myev = &evsp[warp][lane >> 2][(lane & 3) * 4];
            myev[0] = make_float2(ea4.x, ea4.x);
            myev[1] = make_float2(ea4.y, ea4.y);
            myev[2] = make_float2(ea4.z, ea4.z);
            myev[3] = make_float2(ea4.w, ea4.w);
        }
        __syncwarp();

        // EA accumulation: acc[e] packed as 2x f32x2; weights from registers
        ull acc01[8], acc23[8];
#pragma unroll
        for (int e = 0; e < 8; e++) { acc01[e] = 0ull; acc23[e] = 0ull; }
#pragma unroll
        for (int dp = 0; dp < 8; dp++) {
#pragma unroll
            for (int e = 0; e < 8; e++) {
                ulonglong2 ev = *(const ulonglong2*)&evsp[warp][e][2 * dp];
                fma2(acc01[e], ev.x, w01[2 * dp]);
                fma2(acc23[e], ev.x, w23[2 * dp]);
                fma2(acc01[e], ev.y, w01[2 * dp + 1]);
                fma2(acc23[e], ev.y, w23[2 * dp + 1]);
            }
        }

#pragma unroll
        for (int e = 0; e < 8; e++) {
            int me = e0 + e;
            if (me >= ET) break;
            int se = __shfl_sync(0xffffffffu, sreg, e);
            int de = __shfl_sync(0xffffffffu, dreg, 8 + e);
            float4 xl4 = ((const float4*)(g_xl + (size_t)se * 128))[lane];
            uint2 xrh = ((const uint2*)(g_xrh + (size_t)de * 128))[lane];
            float2 xr01 = __half22float2(*(const __half2*)&xrh.x);
            float2 xr23 = __half22float2(*(const __half2*)&xrh.y);
            float2 a = upk(acc01[e]);
            float2 b = upk(acc23[e]);
            float t0 = lrelu(xl4.x + xr01.x + a.x) * att4.x;
            float t1 = lrelu(xl4.y + xr01.y + a.y) * att4.y;
            float t2 = lrelu(xl4.z + xr23.x + b.x) * att4.z;
            float t3 = lrelu(xl4.w + xr23.y + b.y) * att4.w;
            float s = (t0 + t1) + (t2 + t3);
            s += __shfl_xor_sync(0xffffffffu, s, 1);
            s += __shfl_xor_sync(0xffffffffu, s, 2);
            s += __shfl_xor_sync(0xffffffffu, s, 4);
            if ((lane & 7) == 0) {
                int h = lane >> 3;
                float ex = __expf(s);
                g_ex[(size_t)me * 4 + h] = ex;
                atomicAdd(&den[de * 4 + h], ex);
            }
        }
        __syncwarp();
    }
}

// ------ reciprocal of denominators (0.25 head-mean folded in) ------------------
__global__ void k_rcp(float* __restrict__ den) {
    int i = blockIdx.x * blockDim.x + threadIdx.x;
    if (i < NN * HH) den[i] = 0.25f / den[i];
}

// ------ pass C: weighted aggregate, float4 gather + v4 reductions --------------
__global__ void k_aggregate(const int* __restrict__ ei, const float* __restrict__ den,
                            float* __restrict__ outbuf) {
    int tid = threadIdx.x;
    int warp = tid >> 5, lane = tid & 31;
    for (int t = 0; t < 4; t++) {
        int e0 = (blockIdx.x * 32 + t * 8 + warp) * 8;
        if (e0 >= ET) break;
        int sreg = 0, dreg = 0;
        {
            int le = e0 + (lane & 7);
            if (le < ET) {
                if (lane < 8)       sreg = (le < EE) ? ei[le]      : le - EE;
                else if (lane < 16) dreg = (le < EE) ? ei[EE + le] : le - EE;
            }
        }
#pragma unroll
        for (int e = 0; e < 8; e++) {
            int me = e0 + e;
            if (me >= ET) break;
            int se = __shfl_sync(0xffffffffu, sreg, e);
            int de = __shfl_sync(0xffffffffu, dreg, 8 + e);
            float w = 0.f;
            if (lane < 4) w = g_ex[(size_t)me * 4 + lane] * den[de * 4 + lane];  // den = 0.25/sum
            float wl = __shfl_sync(0xffffffffu, w, lane >> 3);
            float4 xl4 = ((const float4*)(g_xl + (size_t)se * 128))[lane];
            float4 p;
            p.x = wl * xl4.x; p.y = wl * xl4.y; p.z = wl * xl4.z; p.w = wl * xl4.w;
            p.x += __shfl_xor_sync(0xffffffffu, p.x, 8);
            p.y += __shfl_xor_sync(0xffffffffu, p.y, 8);
            p.z += __shfl_xor_sync(0xffffffffu, p.z, 8);
            p.w += __shfl_xor_sync(0xffffffffu, p.w, 8);
            p.x += __shfl_xor_sync(0xffffffffu, p.x, 16);
            p.y += __shfl_xor_sync(0xffffffffu, p.y, 16);
            p.z += __shfl_xor_sync(0xffffffffu, p.z, 16);
            p.w += __shfl_xor_sync(0xffffffffu, p.w, 16);
            if (lane < 8) red4(&outbuf[de * 32 + 4 * lane], p);
        }
    }
}

// ------ output head -------------------------------------------------------------
__global__ void k_final(const float* __restrict__ feat, const float* __restrict__ Wout,
                        const float* __restrict__ bout, float* __restrict__ y) {
    __shared__ float WT[32 * 64];   // [c][o]
    int tid = threadIdx.x;
    for (int i = tid; i < 32 * 64; i += blockDim.x) {
        int c = i >> 6, o = i & 63;
        WT[i] = Wout[o * 32 + c];
    }
    __syncthreads();
    int o = tid & 63;
    float bo = bout[o];
#pragma unroll
    for (int it = 0; it < 16; it++) {
        int n = blockIdx.x * 64 + it * 4 + (tid >> 6);
        if (n >= NN) return;
        const float* fr = feat + n * 32;
        float acc = 0.f;
#pragma unroll
        for (int c = 0; c < 32; c++) acc += fr[c] * WT[c * 64 + o];
        acc += bo;
        y[(size_t)n * 64 + o] = lrelu(acc);
    }
}

// =============================================================================
extern "C" void kernel_launch(void* const* d_in, const int* in_sizes, int n_in,
                              void* d_out, int out_size) {
    const float* x     = (const float*)d_in[0];
    const int*   ei    = (const int*)d_in[1];
    const float* eattr = (const float*)d_in[2];
    const float* W0    = (const float*)d_in[3];
    const float* b0    = (const float*)d_in[4];
    const float* bng   = (const float*)d_in[5];
    const float* bnb   = (const float*)d_in[6];
    const float* bnm   = (const float*)d_in[7];
    const float* bnv   = (const float*)d_in[8];
    const float* Wl[2]   = {(const float*)d_in[9],  (const float*)d_in[16]};
    const float* bl[2]   = {(const float*)d_in[10], (const float*)d_in[17]};
    const float* Wr[2]   = {(const float*)d_in[11], (const float*)d_in[18]};
    const float* br[2]   = {(const float*)d_in[12], (const float*)d_in[19]};
    const float* We[2]   = {(const float*)d_in[13], (const float*)d_in[20]};
    const float* att[2]  = {(const float*)d_in[14], (const float*)d_in[21]};
    const float* bias[2] = {(const float*)d_in[15], (const float*)d_in[22]};
    const float* Wout  = (const float*)d_in[23];
    const float* bout  = (const float*)d_in[24];
    float* y = (float*)d_out;

    float *f0, *f1, *f2, *den0, *den1;
    cudaGetSymbolAddress((void**)&f0, g_f0);
    cudaGetSymbolAddress((void**)&f1, g_f1);
    cudaGetSymbolAddress((void**)&f2, g_f2);
    cudaGetSymbolAddress((void**)&den0, g_den);
    den1 = den0 + NN * HH;

    k_embed_plus<<<(NN + 63) / 64, 256>>>(x, W0, b0, bng, bnb, bnm, bnv,
                                          bias[0], bias[1]);                         // 0
    k_loop_accum<<<(EE * 4 + 255) / 256, 256>>>(ei, eattr);                          // 1

    const float* fin[2]  = {f0, f1};
    float*       fden[2] = {den0, den1};
    float*       fout[2] = {f1, f2};
    int gedge = (ET + 255) / 256;   // 8 warps * 8 edges * 4 tiles per block
    for (int l = 0; l < 2; l++) {
        k_xlxr<<<(NN + 31) / 32, 256>>>(fin[l], Wl[l], bl[l], Wr[l], br[l]);         // 2, 6
        k_alpha<<<gedge, 256>>>(ei, eattr, We[l], att[l], fden[l]);                  // 3 <- profiled, 7
        k_rcp<<<(NN * HH + 255) / 256, 256>>>(fden[l]);                              // 4, 8
        k_aggregate<<<gedge, 256>>>(ei, fden[l], fout[l]);                           // 5, 9
    }
    k_final<<<(NN + 63) / 64, 256>>>(f2, Wout, bout, y);                             // 10
}

// round 10
// speedup vs baseline: 1.7059x; 1.1173x over previous
#include <cuda_runtime.h>
#include <cuda_fp16.h>

#define NN 50000
#define EE 800000
#define ET (EE + NN)
#define FD 128      // H*HID
#define EDD 16      // edge_dim
#define HIDD 32
#define HH 4
#define OUTD 64
#define NEGS 0.1f

typedef unsigned long long ull;

// ---------------- scratch (device globals) -----------------------------------
__device__ float  g_f0[NN * HIDD];
__device__ float  g_f1[NN * HIDD];
__device__ float  g_f2[NN * HIDD];
__device__ float  g_xl[(size_t)NN * FD];
__device__ float  g_xr[(size_t)NN * FD];
__device__ __half g_xrh[(size_t)NN * FD];   // fp16 copy of xr for alpha gathers
__device__ float  g_loop[NN * EDD];
__device__ float  g_cnt[NN];
__device__ float  g_ex[(size_t)ET * HH];
__device__ float  g_den[2][NN * HH];

__device__ __forceinline__ float lrelu(float v) { return fmaxf(v, NEGS * v); }

__device__ __forceinline__ void fma2(ull& acc, ull a, ull b) {
    asm("fma.rn.f32x2 %0, %1, %2, %0;" : "+l"(acc) : "l"(a), "l"(b));
}
__device__ __forceinline__ float2 upk(ull v) {
    float2 r; asm("mov.b64 {%0,%1}, %2;" : "=f"(r.x), "=f"(r.y) : "l"(v)); return r;
}
__device__ __forceinline__ ull pkh2(unsigned int h2) {
    float2 f = __half22float2(*(__half2*)&h2);
    ull r; asm("mov.b64 %0, {%1,%2};" : "=l"(r) : "f"(f.x), "f"(f.y)); return r;
}
__device__ __forceinline__ ull splat(float v) {
    ull r; asm("mov.b64 %0, {%1,%1};" : "=l"(r) : "f"(v)); return r;
}
__device__ __forceinline__ void red4(float* addr, float4 v) {
    asm volatile("red.global.add.v4.f32 [%0], {%1,%2,%3,%4};"
                 :: "l"(addr), "f"(v.x), "f"(v.y), "f"(v.z), "f"(v.w) : "memory");
}

// ------ launch 0: embed + zero loop/cnt/den + seed outputs with bias ---------
__global__ void k_embed_plus(const float* __restrict__ x, const float* __restrict__ W0,
                             const float* __restrict__ b0, const float* __restrict__ bng,
                             const float* __restrict__ bnb, const float* __restrict__ bnm,
                             const float* __restrict__ bnv,
                             const float* __restrict__ bias0, const float* __restrict__ bias1) {
    __shared__ float W0t[128 * 32];   // [k][j]
    int tid = threadIdx.x;
    for (int i = tid; i < 128 * 32; i += blockDim.x) {
        int k = i >> 5, j = i & 31;
        W0t[i] = W0[j * 128 + k];
    }
    __syncthreads();
    int warp = tid >> 5, lane = tid & 31;
    float sc = bng[lane] * rsqrtf(bnv[lane] + 1e-5f);
    float bb = bnb[lane], bm = bnm[lane], b00 = b0[lane];
#pragma unroll
    for (int it = 0; it < 8; it++) {
        int n = blockIdx.x * 64 + it * 8 + warp;
        if (n < NN) {
            const float* xr_ = x + (size_t)n * 128;
            float acc = 0.f;
#pragma unroll 8
            for (int k = 0; k < 128; k++) acc += xr_[k] * W0t[k * 32 + lane];
            acc += b00;
            acc = (acc - bm) * sc + bb;
            g_f0[n * 32 + lane] = lrelu(acc);
        }
    }
    // side work: zero accumulators (required for per-call idempotency)
    int gs = blockIdx.x * blockDim.x + tid;
    int stride = gridDim.x * blockDim.x;
    float4 z4 = make_float4(0.f, 0.f, 0.f, 0.f);
    for (int i = gs; i < NN * 4; i += stride) ((float4*)g_loop)[i] = z4;
    for (int i = gs; i < NN; i += stride) g_cnt[i] = 0.f;
    for (int i = gs; i < NN * HH; i += stride) { g_den[0][i] = 0.f; g_den[1][i] = 0.f; }
    for (int i = gs; i < NN * HIDD; i += stride) {
        g_f1[i] = bias0[i & 31];
        g_f2[i] = bias1[i & 31];
    }
}

// ------ launch 1: self-loop attr accumulation (vectorized reds) ---------------
__global__ void k_loop_accum(const int* __restrict__ ei, const float* __restrict__ ea) {
    int i = blockIdx.x * blockDim.x + threadIdx.x;
    if (i >= EE * 4) return;
    int e = i >> 2, q = i & 3;
    int dst = ei[EE + e];
    float4 v = ((const float4*)ea)[i];
    red4(&g_loop[dst * EDD + q * 4], v);
    if (q == 0) atomicAdd(&g_cnt[dst], 1.f);
}

// ------ node transforms (also emits fp16 xr copy) ------------------------------
__global__ void k_xlxr(const float* __restrict__ feat,
                       const float* __restrict__ Wl, const float* __restrict__ bl,
                       const float* __restrict__ Wr, const float* __restrict__ br) {
    __shared__ float WlT[32 * 128];
    __shared__ float WrT[32 * 128];
    __shared__ float tile[32 * 32];
    int tid = threadIdx.x;
    for (int i = tid; i < 32 * 128; i += blockDim.x) {
        int k = i >> 7, j = i & 127;
        WlT[i] = Wl[j * 32 + k];
        WrT[i] = Wr[j * 32 + k];
    }
    int nbase = blockIdx.x * 32;
    for (int i = tid; i < 32 * 32; i += blockDim.x) {
        int n = nbase + (i >> 5);
        tile[i] = (n < NN) ? feat[n * 32 + (i & 31)] : 0.f;
    }
    __syncthreads();
    int j = tid & 127;
    int half = tid >> 7;
    float accl[16], accr[16];
#pragma unroll
    for (int n = 0; n < 16; n++) { accl[n] = 0.f; accr[n] = 0.f; }
#pragma unroll
    for (int k = 0; k < 32; k++) {
        float wl = WlT[k * 128 + j];
        float wr = WrT[k * 128 + j];
        const float* tr = &tile[(half * 16) * 32 + k];
#pragma unroll
        for (int n = 0; n < 16; n++) {
            float fv = tr[n * 32];
            accl[n] += fv * wl;
            accr[n] += fv * wr;
        }
    }
    float blj = bl[j], brj = br[j];
#pragma unroll
    for (int n = 0; n < 16; n++) {
        int node = nbase + half * 16 + n;
        if (node < NN) {
            float xr = accr[n] + brj;
            g_xl[(size_t)node * 128 + j] = accl[n] + blj;
            g_xr[(size_t)node * 128 + j] = xr;
            g_xrh[(size_t)node * 128 + j] = __float2half(xr);
        }
    }
}

// ------ pass A: fp16 smem weights, float4 ev staging, fp16 xr gathers ----------
// lane owns channels 4*lane..4*lane+3 (head = lane>>3); warp does 8 edges; 4 tiles.
#define ALPHA_TILES 4
__global__ __launch_bounds__(256, 3)
void k_alpha(const int* __restrict__ ei, const float* __restrict__ eattr,
             const float* __restrict__ We, const float* __restrict__ att,
             float* __restrict__ den) {
    // WeH[dq][h][lane][k]: d = 4*dq + 2*h + (k>>2), ch = 4*lane + (k&3)
    __shared__ __half WeH[4][2][32][8];              // 4 KB
    __shared__ float4 evs[8][8][4];                  // [warp][edge][dquad] 8 KB
    int tid = threadIdx.x;
    for (int i = tid; i < 2048; i += blockDim.x) {
        int dq = i >> 9, h = (i >> 8) & 1, l = (i >> 3) & 31, k = i & 7;
        int d = 4 * dq + 2 * h + (k >> 2);
        int ch = 4 * l + (k & 3);
        ((__half*)WeH)[i] = __float2half(We[ch * 16 + d]);
    }
    __syncthreads();
    int warp = tid >> 5, lane = tid & 31;
    float4 att4 = ((const float4*)att)[lane];

    for (int t = 0; t < ALPHA_TILES; t++) {
        int e0 = (blockIdx.x * (8 * ALPHA_TILES) + t * 8 + warp) * 8;
        if (e0 >= ET) break;

        // edge indices: lanes 0-7 src, lanes 8-15 dst
        int sreg = 0, dreg = 0;
        {
            int le = e0 + (lane & 7);
            if (le < ET) {
                if (lane < 8)       sreg = (le < EE) ? ei[le]      : le - EE;
                else if (lane < 16) dreg = (le < EE) ? ei[EE + le] : le - EE;
            }
        }
        // stage eattr: lane -> edge = lane>>2, dims 4q..4q+3 (q = lane&3)
        {
            float4 ea4 = make_float4(0.f, 0.f, 0.f, 0.f);
            int ee = e0 + (lane >> 2);
            if (ee < EE) {
                ea4 = ((const float4*)eattr)[(size_t)ee * 4 + (lane & 3)];
            } else if (ee < ET) {
                int n = ee - EE;
                ea4 = ((const float4*)g_loop)[(size_t)n * 4 + (lane & 3)];
                float inv = 1.f / fmaxf(g_cnt[n], 1.f);
                ea4.x *= inv; ea4.y *= inv; ea4.z *= inv; ea4.w *= inv;
            }
            evs[warp][lane >> 2][lane & 3] = ea4;
        }
        __syncwarp();

        // EA accumulation: acc[e] packed as 2x f32x2
        ull acc01[8], acc23[8];
#pragma unroll
        for (int e = 0; e < 8; e++) { acc01[e] = 0ull; acc23[e] = 0ull; }
#pragma unroll
        for (int dq = 0; dq < 4; dq++) {
            uint4 wva = *(const uint4*)&WeH[dq][0][lane][0];   // d = 4dq, 4dq+1
            uint4 wvb = *(const uint4*)&WeH[dq][1][lane][0];   // d = 4dq+2, 4dq+3
            ull w0_01 = pkh2(wva.x), w0_23 = pkh2(wva.y);
            ull w1_01 = pkh2(wva.z), w1_23 = pkh2(wva.w);
            ull w2_01 = pkh2(wvb.x), w2_23 = pkh2(wvb.y);
            ull w3_01 = pkh2(wvb.z), w3_23 = pkh2(wvb.w);
#pragma unroll
            for (int e = 0; e < 8; e++) {
                float4 ev = evs[warp][e][dq];   // broadcast
                ull s0 = splat(ev.x), s1 = splat(ev.y), s2 = splat(ev.z), s3 = splat(ev.w);
                fma2(acc01[e], s0, w0_01); fma2(acc23[e], s0, w0_23);
                fma2(acc01[e], s1, w1_01); fma2(acc23[e], s1, w1_23);
                fma2(acc01[e], s2, w2_01); fma2(acc23[e], s2, w2_23);
                fma2(acc01[e], s3, w3_01); fma2(acc23[e], s3, w3_23);
            }
        }

#pragma unroll
        for (int e = 0; e < 8; e++) {
            int me = e0 + e;
            if (me >= ET) break;
            int se = __shfl_sync(0xffffffffu, sreg, e);
            int de = __shfl_sync(0xffffffffu, dreg, 8 + e);
            float4 xl4 = ((const float4*)(g_xl + (size_t)se * 128))[lane];
            uint2 xrh = ((const uint2*)(g_xrh + (size_t)de * 128))[lane];
            float2 xr01 = __half22float2(*(const __half2*)&xrh.x);
            float2 xr23 = __half22float2(*(const __half2*)&xrh.y);
            float2 a = upk(acc01[e]);
            float2 b = upk(acc23[e]);
            float t0 = lrelu(xl4.x + xr01.x + a.x) * att4.x;
            float t1 = lrelu(xl4.y + xr01.y + a.y) * att4.y;
            float t2 = lrelu(xl4.z + xr23.x + b.x) * att4.z;
            float t3 = lrelu(xl4.w + xr23.y + b.y) * att4.w;
            float s = (t0 + t1) + (t2 + t3);
            s += __shfl_xor_sync(0xffffffffu, s, 1);
            s += __shfl_xor_sync(0xffffffffu, s, 2);
            s += __shfl_xor_sync(0xffffffffu, s, 4);
            if ((lane & 7) == 0) {
                int h = lane >> 3;
                float ex = __expf(s);
                g_ex[(size_t)me * 4 + h] = ex;
                atomicAdd(&den[de * 4 + h], ex);
            }
        }
        __syncwarp();
    }
}

// ------ reciprocal of denominators (0.25 head-mean folded in) ------------------
__global__ void k_rcp(float* __restrict__ den) {
    int i = blockIdx.x * blockDim.x + threadIdx.x;
    if (i < NN * HH) den[i] = 0.25f / den[i];
}

// ------ pass C: weighted aggregate, float4 gather + v4 reductions --------------
__global__ void k_aggregate(const int* __restrict__ ei, const float* __restrict__ den,
                            float* __restrict__ outbuf) {
    int tid = threadIdx.x;
    int warp = tid >> 5, lane = tid & 31;
    for (int t = 0; t < 4; t++) {
        int e0 = (blockIdx.x * 32 + t * 8 + warp) * 8;
        if (e0 >= ET) break;
        int sreg = 0, dreg = 0;
        {
            int le = e0 + (lane & 7);
            if (le < ET) {
                if (lane < 8)       sreg = (le < EE) ? ei[le]      : le - EE;
                else if (lane < 16) dreg = (le < EE) ? ei[EE + le] : le - EE;
            }
        }
#pragma unroll
        for (int e = 0; e < 8; e++) {
            int me = e0 + e;
            if (me >= ET) break;
            int se = __shfl_sync(0xffffffffu, sreg, e);
            int de = __shfl_sync(0xffffffffu, dreg, 8 + e);
            float w = 0.f;
            if (lane < 4) w = g_ex[(size_t)me * 4 + lane] * den[de * 4 + lane];  // den = 0.25/sum
            float wl = __shfl_sync(0xffffffffu, w, lane >> 3);
            float4 xl4 = ((const float4*)(g_xl + (size_t)se * 128))[lane];
            float4 p;
            p.x = wl * xl4.x; p.y = wl * xl4.y; p.z = wl * xl4.z; p.w = wl * xl4.w;
            p.x += __shfl_xor_sync(0xffffffffu, p.x, 8);
            p.y += __shfl_xor_sync(0xffffffffu, p.y, 8);
            p.z += __shfl_xor_sync(0xffffffffu, p.z, 8);
            p.w += __shfl_xor_sync(0xffffffffu, p.w, 8);
            p.x += __shfl_xor_sync(0xffffffffu, p.x, 16);
            p.y += __shfl_xor_sync(0xffffffffu, p.y, 16);
            p.z += __shfl_xor_sync(0xffffffffu, p.z, 16);
            p.w += __shfl_xor_sync(0xffffffffu, p.w, 16);
            if (lane < 8) red4(&outbuf[de * 32 + 4 * lane], p);
        }
    }
}

// ------ output head -------------------------------------------------------------
__global__ void k_final(const float* __restrict__ feat, const float* __restrict__ Wout,
                        const float* __restrict__ bout, float* __restrict__ y) {
    __shared__ float WT[32 * 64];   // [c][o]
    int tid = threadIdx.x;
    for (int i = tid; i < 32 * 64; i += blockDim.x) {
        int c = i >> 6, o = i & 63;
        WT[i] = Wout[o * 32 + c];
    }
    __syncthreads();
    int o = tid & 63;
    float bo = bout[o];
#pragma unroll
    for (int it = 0; it < 16; it++) {
        int n = blockIdx.x * 64 + it * 4 + (tid >> 6);
        if (n >= NN) return;
        const float* fr = feat + n * 32;
        float acc = 0.f;
#pragma unroll
        for (int c = 0; c < 32; c++) acc += fr[c] * WT[c * 64 + o];
        acc += bo;
        y[(size_t)n * 64 + o] = lrelu(acc);
    }
}

// =============================================================================
extern "C" void kernel_launch(void* const* d_in, const int* in_sizes, int n_in,
                              void* d_out, int out_size) {
    const float* x     = (const float*)d_in[0];
    const int*   ei    = (const int*)d_in[1];
    const float* eattr = (const float*)d_in[2];
    const float* W0    = (const float*)d_in[3];
    const float* b0    = (const float*)d_in[4];
    const float* bng   = (const float*)d_in[5];
    const float* bnb   = (const float*)d_in[6];
    const float* bnm   = (const float*)d_in[7];
    const float* bnv   = (const float*)d_in[8];
    const float* Wl[2]   = {(const float*)d_in[9],  (const float*)d_in[16]};
    const float* bl[2]   = {(const float*)d_in[10], (const float*)d_in[17]};
    const float* Wr[2]   = {(const float*)d_in[11], (const float*)d_in[18]};
    const float* br[2]   = {(const float*)d_in[12], (const float*)d_in[19]};
    const float* We[2]   = {(const float*)d_in[13], (const float*)d_in[20]};
    const float* att[2]  = {(const float*)d_in[14], (const float*)d_in[21]};
    const float* bias[2] = {(const float*)d_in[15], (const float*)d_in[22]};
    const float* Wout  = (const float*)d_in[23];
    const float* bout  = (const float*)d_in[24];
    float* y = (float*)d_out;

    float *f0, *f1, *f2, *den0, *den1;
    cudaGetSymbolAddress((void**)&f0, g_f0);
    cudaGetSymbolAddress((void**)&f1, g_f1);
    cudaGetSymbolAddress((void**)&f2, g_f2);
    cudaGetSymbolAddress((void**)&den0, g_den);
    den1 = den0 + NN * HH;

    k_embed_plus<<<(NN + 63) / 64, 256>>>(x, W0, b0, bng, bnb, bnm, bnv,
                                          bias[0], bias[1]);                         // 0
    k_loop_accum<<<(EE * 4 + 255) / 256, 256>>>(ei, eattr);                          // 1

    const float* fin[2]  = {f0, f1};
    float*       fden[2] = {den0, den1};
    float*       fout[2] = {f1, f2};
    int gedge = (ET + 255) / 256;   // 8 warps * 8 edges * 4 tiles per block
    for (int l = 0; l < 2; l++) {
        k_xlxr<<<(NN + 31) / 32, 256>>>(fin[l], Wl[l], bl[l], Wr[l], br[l]);         // 2, 6
        k_alpha<<<gedge, 256>>>(ei, eattr, We[l], att[l], fden[l]);                  // 3 <- profiled, 7
        k_rcp<<<(NN * HH + 255) / 256, 256>>>(fden[l]);                              // 4, 8
        k_aggregate<<<gedge, 256>>>(ei, fden[l], fout[l]);                           // 5, 9
    }
    k_final<<<(NN + 63) / 64, 256>>>(f2, Wout, bout, y);                             // 10
}